// round 7
// baseline (speedup 1.0000x reference)
#include <cuda_runtime.h>
#include <cuda_bf16.h>
#include <mma.h>
#include <math.h>
#include <stdint.h>

using namespace nvcuda;

// ---------------- scratch (allocation-free: __device__ globals) ----------------
__device__ float g_bufA[660000];
__device__ float g_bufB[660000];
__device__ float g_h[100 * 512];
__device__ float g_q[4 * 100 * 128];
__device__ float g_k[4 * 100 * 128];
__device__ float g_v[4 * 100 * 256];
__device__ float g_ocat[100 * 1024];
__device__ float g_ffn[100 * 2048];
__device__ float g_part[819200];   // split-K partials (max 4x100x2048)

// ================= HMMA (mma.sync bf16, 3-term split) GEMM ====================
// CTA: 128 threads (4 warps), tile M=64 x N=64, K chunks of 64.
// Split-bf16: a = ah + al, C += Ah*Bh + Ah*Bl + Al*Bh in fp32.
// Register-prefetch pipeline: chunk k+1 LDGs issue before chunk k MMA.
struct __align__(32) HSM {
    __nv_bfloat16 Ah[64 * 80];
    __nv_bfloat16 Al[64 * 80];
    __nv_bfloat16 Bh[64 * 80];
    __nv_bfloat16 Bl[64 * 80];
};
union __align__(32) HU {
    HSM s;
    float C[64 * 64];
};

__device__ __forceinline__ uint32_t bf2pack(__nv_bfloat16 a, __nv_bfloat16 b) {
    __nv_bfloat162 t(a, b);
    return *reinterpret_cast<uint32_t*>(&t);
}

template <bool NKW>
__device__ __forceinline__ void hmma_core(
    HU& u, const float* __restrict__ A, int K,
    const float* __restrict__ B, int ldB, int nk, int mvalid)
{
    const int t = threadIdx.x;
    const int wid = t >> 5;
    const int wm = wid >> 1, wn = wid & 1;
    const int rbase = t >> 4;          // row base (A row / B row)
    const int c4 = (t & 15) << 2;      // column (k or n) *4
    const float4 z4 = make_float4(0.f, 0.f, 0.f, 0.f);

    wmma::fragment<wmma::accumulator, 16, 16, 16, float> c[2][2];
#pragma unroll
    for (int i = 0; i < 2; i++)
#pragma unroll
        for (int j = 0; j < 2; j++) wmma::fill_fragment(c[i][j], 0.0f);

    float4 pa[8], pb[8];

    // prefetch chunk 0
    {
        const int k0 = 0;
#pragma unroll
        for (int i = 0; i < 8; i++) {
            const int m = rbase + 8 * i;
            pa[i] = (m < mvalid) ? *(const float4*)(A + (size_t)m * K + k0 + c4) : z4;
        }
#pragma unroll
        for (int i = 0; i < 8; i++) {
            const int r = rbase + 8 * i;
            pb[i] = NKW ? *(const float4*)(B + (size_t)r * ldB + k0 + c4)
                        : *(const float4*)(B + (size_t)(k0 + r) * ldB + c4);
        }
    }

    for (int kt = 0; kt < nk; kt++) {
        // ---- store prefetched chunk to smem (convert fp32 -> hi/lo bf16) ----
#pragma unroll
        for (int i = 0; i < 8; i++) {
            const int m = rbase + 8 * i;
            const float4 v = pa[i];
            const __nv_bfloat16 h0 = __float2bfloat16_rn(v.x), h1 = __float2bfloat16_rn(v.y),
                                h2 = __float2bfloat16_rn(v.z), h3 = __float2bfloat16_rn(v.w);
            uint2 uh, ul;
            uh.x = bf2pack(h0, h1); uh.y = bf2pack(h2, h3);
            ul.x = bf2pack(__float2bfloat16_rn(v.x - __bfloat162float(h0)),
                           __float2bfloat16_rn(v.y - __bfloat162float(h1)));
            ul.y = bf2pack(__float2bfloat16_rn(v.z - __bfloat162float(h2)),
                           __float2bfloat16_rn(v.w - __bfloat162float(h3)));
            *(uint2*)&u.s.Ah[m * 80 + c4] = uh;
            *(uint2*)&u.s.Al[m * 80 + c4] = ul;
        }
#pragma unroll
        for (int i = 0; i < 8; i++) {
            const int r = rbase + 8 * i;
            const float4 v = pb[i];
            if (!NKW) {
                const __nv_bfloat16 h0 = __float2bfloat16_rn(v.x), h1 = __float2bfloat16_rn(v.y),
                                    h2 = __float2bfloat16_rn(v.z), h3 = __float2bfloat16_rn(v.w);
                uint2 uh, ul;
                uh.x = bf2pack(h0, h1); uh.y = bf2pack(h2, h3);
                ul.x = bf2pack(__float2bfloat16_rn(v.x - __bfloat162float(h0)),
                               __float2bfloat16_rn(v.y - __bfloat162float(h1)));
                ul.y = bf2pack(__float2bfloat16_rn(v.z - __bfloat162float(h2)),
                               __float2bfloat16_rn(v.w - __bfloat162float(h3)));
                *(uint2*)&u.s.Bh[r * 80 + c4] = uh;
                *(uint2*)&u.s.Bl[r * 80 + c4] = ul;
            } else {
                const float vv[4] = {v.x, v.y, v.z, v.w};
#pragma unroll
                for (int j = 0; j < 4; j++) {
                    const __nv_bfloat16 hb = __float2bfloat16_rn(vv[j]);
                    u.s.Bh[(c4 + j) * 80 + r] = hb;
                    u.s.Bl[(c4 + j) * 80 + r] =
                        __float2bfloat16_rn(vv[j] - __bfloat162float(hb));
                }
            }
        }
        __syncthreads();
        // ---- issue next chunk's LDGs (hide behind MMA) ----
        if (kt + 1 < nk) {
            const int k0 = (kt + 1) << 6;
#pragma unroll
            for (int i = 0; i < 8; i++) {
                const int m = rbase + 8 * i;
                pa[i] = (m < mvalid) ? *(const float4*)(A + (size_t)m * K + k0 + c4) : z4;
            }
#pragma unroll
            for (int i = 0; i < 8; i++) {
                const int r = rbase + 8 * i;
                pb[i] = NKW ? *(const float4*)(B + (size_t)r * ldB + k0 + c4)
                            : *(const float4*)(B + (size_t)(k0 + r) * ldB + c4);
            }
        }
        // ---- compute: 4 k16-steps, 3-term ----
#pragma unroll
        for (int kk = 0; kk < 4; kk++) {
            wmma::fragment<wmma::matrix_a, 16, 16, 16, __nv_bfloat16, wmma::row_major> ah[2], al[2];
            wmma::fragment<wmma::matrix_b, 16, 16, 16, __nv_bfloat16, wmma::row_major> bh[2], bl[2];
#pragma unroll
            for (int i = 0; i < 2; i++) {
                wmma::load_matrix_sync(ah[i], &u.s.Ah[(wm * 32 + i * 16) * 80 + kk * 16], 80);
                wmma::load_matrix_sync(al[i], &u.s.Al[(wm * 32 + i * 16) * 80 + kk * 16], 80);
            }
#pragma unroll
            for (int j = 0; j < 2; j++) {
                wmma::load_matrix_sync(bh[j], &u.s.Bh[(kk * 16) * 80 + wn * 32 + j * 16], 80);
                wmma::load_matrix_sync(bl[j], &u.s.Bl[(kk * 16) * 80 + wn * 32 + j * 16], 80);
            }
#pragma unroll
            for (int i = 0; i < 2; i++)
#pragma unroll
                for (int j = 0; j < 2; j++) {
                    wmma::mma_sync(c[i][j], ah[i], bh[j], c[i][j]);
                    wmma::mma_sync(c[i][j], ah[i], bl[j], c[i][j]);
                    wmma::mma_sync(c[i][j], al[i], bh[j], c[i][j]);
                }
        }
        __syncthreads();
    }
#pragma unroll
    for (int i = 0; i < 2; i++)
#pragma unroll
        for (int j = 0; j < 2; j++)
            wmma::store_matrix_sync(&u.C[(wm * 32 + i * 16) * 64 + wn * 32 + j * 16],
                                    c[i][j], 64, wmma::mem_row_major);
    __syncthreads();
}

// split-K GEMM: grid(2, N/64, S); partials to part[s][100][N]
template <bool NKW>
__global__ __launch_bounds__(128) void hmma_split_kernel(
    const float* __restrict__ A, const float* __restrict__ B,
    float* __restrict__ part, int N, int K, int S)
{
    __shared__ HU u;
    const int m0 = blockIdx.x * 64, n0 = blockIdx.y * 64, s = blockIdx.z;
    const int klen = K / S, kstart = s * klen;
    const float* Ap = A + (size_t)m0 * K + kstart;
    const float* Bp = NKW ? (B + (size_t)n0 * K + kstart) : (B + (size_t)kstart * N + n0);
    hmma_core<NKW>(u, Ap, K, Bp, NKW ? K : N, klen >> 6, 100 - m0);
    float* P = part + ((size_t)s * 100 + m0) * N + n0;
    const int t = threadIdx.x;
#pragma unroll
    for (int i = 0; i < 8; i++) {
        const int e = t + (i << 7);
        const int m = e >> 4, n4 = (e & 15) << 2;
        if (m0 + m < 100)
            *(float4*)&P[(size_t)m * N + n4] = *(float4*)&u.C[m * 64 + n4];
    }
}

// combine: out = sum_s part[s] (+bias)(relu)(+resid). Deterministic fixed order.
__global__ __launch_bounds__(256) void combine_kernel(
    const float* __restrict__ part, int S, int N,
    const float* __restrict__ bias, const float* __restrict__ resid,
    float* __restrict__ out, int relu)
{
    const int idx = (blockIdx.x * 256 + threadIdx.x) * 4;
    if (idx >= 100 * N) return;
    const int n = idx % N;
    float4 v = *(const float4*)&part[idx];
    for (int s = 1; s < S; s++) {
        const float4 p = *(const float4*)&part[(size_t)s * 100 * N + idx];
        v.x += p.x; v.y += p.y; v.z += p.z; v.w += p.w;
    }
    if (bias) {
        const float4 b = *(const float4*)&bias[n];
        v.x += b.x; v.y += b.y; v.z += b.z; v.w += b.w;
    }
    if (relu) {
        v.x = fmaxf(v.x, 0.f); v.y = fmaxf(v.y, 0.f);
        v.z = fmaxf(v.z, 0.f); v.w = fmaxf(v.w, 0.f);
    }
    if (resid) {
        const float4 r = *(const float4*)&resid[idx];
        v.x += r.x; v.y += r.y; v.z += r.z; v.w += r.w;
    }
    *(float4*)&out[idx] = v;
}

// QKV: grid(2, 4, 12). z<4: Q head z (scale 0.1); z<8: K; else V. K=512, no split.
__global__ __launch_bounds__(128) void hmma_qkv_kernel(
    const float* __restrict__ h, const float* __restrict__ Wq,
    const float* __restrict__ Wk, const float* __restrict__ Wv)
{
    const int z = blockIdx.z;
    const float* B;
    float* C;
    int Nc;
    float scale = 1.0f;
    if (z < 4)      { Nc = 128; B = Wq + (size_t)z * 65536;        C = g_q + z * 12800; scale = 0.1f; }
    else if (z < 8) { Nc = 128; B = Wk + (size_t)(z - 4) * 65536;  C = g_k + (z - 4) * 12800; }
    else            { Nc = 256; B = Wv + (size_t)(z - 8) * 131072; C = g_v + (z - 8) * 25600; }
    const int n0 = blockIdx.y * 64;
    if (n0 >= Nc) return;
    const int m0 = blockIdx.x * 64;
    __shared__ HU u;
    hmma_core<false>(u, h + (size_t)m0 * 512, 512, B + n0, Nc, 8, 100 - m0);
    float* Cp = C + (size_t)m0 * Nc + n0;
    const int t = threadIdx.x;
#pragma unroll
    for (int i = 0; i < 8; i++) {
        const int e = t + (i << 7);
        const int m = e >> 4, n4 = (e & 15) << 2;
        if (m0 + m < 100) {
            float4 v = *(float4*)&u.C[m * 64 + n4];
            v.x *= scale; v.y *= scale; v.z *= scale; v.w *= scale;
            *(float4*)&Cp[(size_t)m * Nc + n4] = v;
        }
    }
}

// ---------------- conv layers 1-9 (row-strip kernel) ----------------
template <int CIN, int HIN, int COUT, int KS, int COG, bool RELU, bool FIRST>
__global__ __launch_bounds__(128) void conv_kernel(
    const float* __restrict__ in, const float* __restrict__ W,
    const float* __restrict__ bias, float* __restrict__ out)
{
    constexpr int HOUT = HIN - KS + 1;
    constexpr int WOUT = HOUT;
    constexpr int INSZ = CIN * HIN * HIN;
    constexpr int HW = HOUT * WOUT;
    __shared__ float sin_[INSZ];

    const int p = blockIdx.x;
    const int co0 = blockIdx.y * COG;

    if (FIRST) {
        const int ib = p / 10, jb = p % 10;
        for (int idx = threadIdx.x; idx < INSZ; idx += blockDim.x) {
            const int c = idx / (HIN * HIN);
            const int rem = idx % (HIN * HIN);
            const int r = rem / HIN, cc = rem % HIN;
            sin_[idx] = in[c * 40000 + (20 * jb + r) * 200 + (20 * ib + cc)];
        }
    } else {
        const float* src = in + p * INSZ;
        for (int idx = threadIdx.x; idx < INSZ; idx += blockDim.x)
            sin_[idx] = src[idx];
    }
    __syncthreads();

    for (int pair = threadIdx.x; pair < COG * HOUT; pair += blockDim.x) {
        const int co = co0 + pair / HOUT;
        const int py = pair % HOUT;
        float acc[WOUT];
        const float bv = bias[co];
#pragma unroll
        for (int px = 0; px < WOUT; px++) acc[px] = bv;
        const float* wbase = W + co * CIN * KS * KS;
        for (int ci = 0; ci < CIN; ci++) {
#pragma unroll
            for (int ky = 0; ky < KS; ky++) {
                const float* irow = sin_ + ci * HIN * HIN + (py + ky) * HIN;
                float w[KS];
#pragma unroll
                for (int kx = 0; kx < KS; kx++)
                    w[kx] = wbase[ci * KS * KS + ky * KS + kx];
#pragma unroll
                for (int px = 0; px < WOUT; px++) {
#pragma unroll
                    for (int kx = 0; kx < KS; kx++)
                        acc[px] += w[kx] * irow[px + kx];
                }
            }
        }
        float* orow = out + p * COUT * HW + co * HW + py * WOUT;
#pragma unroll
        for (int px = 0; px < WOUT; px++) {
            float v = acc[px];
            if (RELU) v = fmaxf(v, 0.0f);
            orow[px] = v;
        }
    }
}

// ---------------- location embedding add ----------------
__global__ __launch_bounds__(256) void locadd_kernel(const float* __restrict__ conv_out,
                                                     float* __restrict__ h)
{
    int i = blockIdx.x * blockDim.x + threadIdx.x;
    if (i >= 100 * 512) return;
    const int n = i >> 9;
    const int d = i & 511;
    const float pos = 20.0f * (float)(n / 10);
    const int k = d & 255;
    const float ang = pos * exp2f(-0.10381025296523009f * (float)k);
    const float e = (d < 256) ? sinf(ang) : cosf(ang);
    h[i] = conv_out[i] + e;
}

// ---------------- attention v2: warp-per-row (Q pre-scaled by 0.1) -----------
// grid (4 heads, 10 rowgroups), 320 threads = 10 warps, warp w -> row rg*10+w.
// smem: ks[100*132] | vs[100*256] | qs[10*132] | prow[10*104]
#define ATTN_SMEM ((100 * 132 + 100 * 256 + 10 * 132 + 10 * 104) * 4)
__global__ __launch_bounds__(320) void attn_kernel()
{
    extern __shared__ float sm[];
    float* ks = sm;
    float* vs = sm + 100 * 132;
    float* qs = vs + 100 * 256;
    float* prow = qs + 10 * 132;

    const int h = blockIdx.x;
    const int rg = blockIdx.y;
    const int tid = threadIdx.x;
    const int w = tid >> 5, lane = tid & 31;

    for (int idx = tid; idx < 100 * 128; idx += 320) {
        const int m = idx >> 7, d = idx & 127;
        ks[m * 132 + d] = g_k[h * 12800 + idx];
    }
    for (int idx = tid; idx < 100 * 256; idx += 320)
        vs[idx] = g_v[h * 25600 + idx];
    for (int idx = tid; idx < 10 * 128; idx += 320) {
        const int r = idx >> 7, d = idx & 127;
        qs[r * 132 + d] = g_q[(h * 100 + rg * 10 + r) * 128 + d];
    }
    __syncthreads();

    // ---- scores: lane handles keys lane, lane+32, lane+64, lane+96 ----
    const float4* q4 = (const float4*)(qs + w * 132);
    float sc[4];
#pragma unroll
    for (int j = 0; j < 4; j++) {
        const int m = lane + 32 * j;
        if (m < 100) {
            const float4* k4 = (const float4*)(ks + m * 132);
            float acc = 0.0f;
#pragma unroll
            for (int dd = 0; dd < 32; dd++) {
                const float4 kv = k4[dd];
                const float4 qv = q4[dd];
                acc += qv.x * kv.x + qv.y * kv.y + qv.z * kv.z + qv.w * kv.w;
            }
            sc[j] = acc;
        } else sc[j] = -1e30f;
    }
    // ---- softmax over 100 (warp-local) ----
    float mx = fmaxf(fmaxf(sc[0], sc[1]), fmaxf(sc[2], sc[3]));
#pragma unroll
    for (int o = 16; o; o >>= 1) mx = fmaxf(mx, __shfl_xor_sync(0xffffffffu, mx, o));
    float e[4], sum = 0.0f;
#pragma unroll
    for (int j = 0; j < 4; j++) { e[j] = __expf(sc[j] - mx); sum += e[j]; }
#pragma unroll
    for (int o = 16; o; o >>= 1) sum += __shfl_xor_sync(0xffffffffu, sum, o);
    const float inv = 1.0f / sum;
#pragma unroll
    for (int j = 0; j < 4; j++) {
        const int m = lane + 32 * j;
        if (m < 100) prow[w * 104 + m] = e[j] * inv;
    }
    __syncwarp();

    // ---- O: lane accumulates dims lane+32*j over 100 keys ----
    float acc[8] = {};
    const float* pr = prow + w * 104;
#pragma unroll 4
    for (int m = 0; m < 100; m++) {
        const float p = pr[m];
        const float* vr = vs + m * 256 + lane;
#pragma unroll
        for (int j = 0; j < 8; j++) acc[j] += p * vr[32 * j];
    }
    const int n = rg * 10 + w;
    float* orow = g_ocat + n * 1024 + h * 256 + lane;
#pragma unroll
    for (int j = 0; j < 8; j++) orow[32 * j] = acc[j];
}

// ---------------- launch ----------------
extern "C" void kernel_launch(void* const* d_in, const int* in_sizes, int n_in,
                              void* d_out, int out_size)
{
    (void)in_sizes; (void)n_in; (void)out_size;
    const float* x = (const float*)d_in[0];
    const float* cw[10];
    const float* cb[10];
    for (int i = 0; i < 10; i++) {
        cw[i] = (const float*)d_in[1 + 2 * i];
        cb[i] = (const float*)d_in[2 + 2 * i];
    }
    const float* Wq = (const float*)d_in[21];
    const float* Wk = (const float*)d_in[22];
    const float* Wv = (const float*)d_in[23];
    const float* Wo = (const float*)d_in[24];
    const float* W1 = (const float*)d_in[25];
    const float* b1 = (const float*)d_in[26];
    const float* W2 = (const float*)d_in[27];
    const float* b2 = (const float*)d_in[28];

    float *bufA, *bufB, *h, *ocat, *ffn, *part;
    cudaGetSymbolAddress((void**)&bufA, g_bufA);
    cudaGetSymbolAddress((void**)&bufB, g_bufB);
    cudaGetSymbolAddress((void**)&h, g_h);
    cudaGetSymbolAddress((void**)&ocat, g_ocat);
    cudaGetSymbolAddress((void**)&ffn, g_ffn);
    cudaGetSymbolAddress((void**)&part, g_part);

    cudaFuncSetAttribute(attn_kernel, cudaFuncAttributeMaxDynamicSharedMemorySize, ATTN_SMEM);

    // Conv stack (RELU_AFTER = F T F T T T T T T F); conv10 = HMMA BT-GEMM.
    conv_kernel<3, 20, 8, 3, 8, false, true><<<dim3(100, 1), 128>>>(x, cw[0], cb[0], bufA);
    conv_kernel<8, 18, 16, 3, 8, true, false><<<dim3(100, 2), 128>>>(bufA, cw[1], cb[1], bufB);
    conv_kernel<16, 16, 32, 3, 8, false, false><<<dim3(100, 4), 128>>>(bufB, cw[2], cb[2], bufA);
    conv_kernel<32, 14, 32, 3, 8, true, false><<<dim3(100, 4), 128>>>(bufA, cw[3], cb[3], bufB);
    conv_kernel<32, 12, 64, 3, 16, true, false><<<dim3(100, 4), 128>>>(bufB, cw[4], cb[4], bufA);
    conv_kernel<64, 10, 64, 3, 16, true, false><<<dim3(100, 4), 128>>>(bufA, cw[5], cb[5], bufB);
    conv_kernel<64, 8, 128, 3, 32, true, false><<<dim3(100, 4), 128>>>(bufB, cw[6], cb[6], bufA);
    conv_kernel<128, 6, 128, 3, 32, true, false><<<dim3(100, 4), 128>>>(bufA, cw[7], cb[7], bufB);
    conv_kernel<128, 4, 256, 3, 64, true, false><<<dim3(100, 4), 128>>>(bufB, cw[8], cb[8], bufA);
    // conv10: [100,1024] @ W10^T + b10  (S=8)
    hmma_split_kernel<true><<<dim3(2, 8, 8), 128>>>(bufA, cw[9], part, 512, 1024, 8);
    combine_kernel<<<50, 256>>>(part, 8, 512, cb[9], nullptr, bufB, 0);

    locadd_kernel<<<200, 256>>>(bufB, h);

    for (int n = 0; n < 12; n++) {
        hmma_qkv_kernel<<<dim3(2, 4, 12), 128>>>(h, Wq + (size_t)n * 262144,
                                                 Wk + (size_t)n * 262144,
                                                 Wv + (size_t)n * 524288);
        attn_kernel<<<dim3(4, 10), 320, ATTN_SMEM>>>();
        // h = h + ocat @ Wo   (S=8)
        hmma_split_kernel<false><<<dim3(2, 8, 8), 128>>>(ocat, Wo + (size_t)n * 524288,
                                                         part, 512, 1024, 8);
        combine_kernel<<<50, 256>>>(part, 8, 512, nullptr, h, h, 0);
        // ffn = relu(h @ W1 + b1)   (S=4)
        hmma_split_kernel<false><<<dim3(2, 32, 4), 128>>>(h, W1 + (size_t)n * 1048576,
                                                          part, 2048, 512, 4);
        combine_kernel<<<200, 256>>>(part, 4, 2048, b1 + (size_t)n * 2048, nullptr, ffn, 1);
        // h = h + ffn @ W2 + b2   (S=8; last layer -> d_out)
        float* outp = (n == 11) ? (float*)d_out : h;
        hmma_split_kernel<false><<<dim3(2, 8, 8), 128>>>(ffn, W2 + (size_t)n * 1048576,
                                                         part, 512, 2048, 8);
        combine_kernel<<<50, 256>>>(part, 8, 512, b2 + (size_t)n * 512, h, outp, 0);
    }
}

// round 9
// speedup vs baseline: 1.1811x; 1.1811x over previous
#include <cuda_runtime.h>
#include <cuda_bf16.h>
#include <mma.h>
#include <math.h>
#include <stdint.h>

using namespace nvcuda;

// ---------------- scratch (allocation-free: __device__ globals) ----------------
__device__ float g_bufA[660000];
__device__ float g_bufB[660000];
__device__ float g_h[100 * 512];
__device__ float g_q[4 * 100 * 128];
__device__ float g_k[4 * 100 * 128];
__device__ float g_v[4 * 100 * 256];
__device__ float g_ocat[100 * 1024];
__device__ float g_ffn[100 * 2048];
__device__ float g_part[819200];
__device__ int g_count = 0;
__device__ volatile int g_sense = 0;

#define NCTA 128
#define NTHR 128
#define DSM_BYTES 168960

// ---------------- global barrier (sense-reversing; even count per launch) ----
__device__ __forceinline__ void gbar(int* lsense) {
    __syncthreads();
    if (threadIdx.x == 0) {
        __threadfence();
        *lsense ^= 1;
        if (atomicAdd(&g_count, 1) == NCTA - 1) {
            g_count = 0;
            __threadfence();
            g_sense = *lsense;
        } else {
            while (g_sense != *lsense) __nanosleep(64);
        }
        __threadfence();
    }
    __syncthreads();
}

// ================= HMMA core (R6-proven serial staging) =======================
struct __align__(32) HSM {
    __nv_bfloat16 Ah[64 * 80];
    __nv_bfloat16 Al[64 * 80];
    __nv_bfloat16 Bh[64 * 80];
    __nv_bfloat16 Bl[64 * 80];
};
union __align__(32) HU {
    HSM s;
    float C[64 * 64];
};

__device__ __forceinline__ uint32_t bf2pack(__nv_bfloat16 a, __nv_bfloat16 b) {
    __nv_bfloat162 t(a, b);
    return *reinterpret_cast<uint32_t*>(&t);
}

template <bool NKW>
__device__ __forceinline__ void hmma_core(
    HU& u, const float* __restrict__ A, int K,
    const float* __restrict__ B, int ldB, int nk, int mvalid)
{
    const int t = threadIdx.x;
    const int wid = t >> 5;
    const int wm = wid >> 1, wn = wid & 1;

    wmma::fragment<wmma::accumulator, 16, 16, 16, float> c[2][2];
#pragma unroll
    for (int i = 0; i < 2; i++)
#pragma unroll
        for (int j = 0; j < 2; j++) wmma::fill_fragment(c[i][j], 0.0f);

    for (int kt = 0; kt < nk; kt++) {
        const int k0 = kt << 6;
#pragma unroll
        for (int i = 0; i < 8; i++) {
            const int e = t + (i << 7);
            const int m = e >> 4, k4 = (e & 15) << 2;
            float4 v = make_float4(0.f, 0.f, 0.f, 0.f);
            if (m < mvalid) v = *(const float4*)(A + (size_t)m * K + k0 + k4);
            const __nv_bfloat16 h0 = __float2bfloat16_rn(v.x), h1 = __float2bfloat16_rn(v.y),
                                h2 = __float2bfloat16_rn(v.z), h3 = __float2bfloat16_rn(v.w);
            uint2 uh, ul;
            uh.x = bf2pack(h0, h1); uh.y = bf2pack(h2, h3);
            ul.x = bf2pack(__float2bfloat16_rn(v.x - __bfloat162float(h0)),
                           __float2bfloat16_rn(v.y - __bfloat162float(h1)));
            ul.y = bf2pack(__float2bfloat16_rn(v.z - __bfloat162float(h2)),
                           __float2bfloat16_rn(v.w - __bfloat162float(h3)));
            *(uint2*)&u.s.Ah[m * 80 + k4] = uh;
            *(uint2*)&u.s.Al[m * 80 + k4] = ul;
        }
#pragma unroll
        for (int i = 0; i < 8; i++) {
            const int e = t + (i << 7);
            if (!NKW) {
                const int k = e >> 4, n4 = (e & 15) << 2;
                const float4 v = *(const float4*)(B + (size_t)(k0 + k) * ldB + n4);
                const __nv_bfloat16 h0 = __float2bfloat16_rn(v.x), h1 = __float2bfloat16_rn(v.y),
                                    h2 = __float2bfloat16_rn(v.z), h3 = __float2bfloat16_rn(v.w);
                uint2 uh, ul;
                uh.x = bf2pack(h0, h1); uh.y = bf2pack(h2, h3);
                ul.x = bf2pack(__float2bfloat16_rn(v.x - __bfloat162float(h0)),
                               __float2bfloat16_rn(v.y - __bfloat162float(h1)));
                ul.y = bf2pack(__float2bfloat16_rn(v.z - __bfloat162float(h2)),
                               __float2bfloat16_rn(v.w - __bfloat162float(h3)));
                *(uint2*)&u.s.Bh[k * 80 + n4] = uh;
                *(uint2*)&u.s.Bl[k * 80 + n4] = ul;
            } else {
                const int n = e >> 4, k4 = (e & 15) << 2;
                const float4 v = *(const float4*)(B + (size_t)n * ldB + k0 + k4);
                const float vv[4] = {v.x, v.y, v.z, v.w};
#pragma unroll
                for (int j = 0; j < 4; j++) {
                    const __nv_bfloat16 hb = __float2bfloat16_rn(vv[j]);
                    u.s.Bh[(k4 + j) * 80 + n] = hb;
                    u.s.Bl[(k4 + j) * 80 + n] =
                        __float2bfloat16_rn(vv[j] - __bfloat162float(hb));
                }
            }
        }
        __syncthreads();
#pragma unroll
        for (int kk = 0; kk < 4; kk++) {
            wmma::fragment<wmma::matrix_a, 16, 16, 16, __nv_bfloat16, wmma::row_major> ah[2], al[2];
            wmma::fragment<wmma::matrix_b, 16, 16, 16, __nv_bfloat16, wmma::row_major> bh[2], bl[2];
#pragma unroll
            for (int i = 0; i < 2; i++) {
                wmma::load_matrix_sync(ah[i], &u.s.Ah[(wm * 32 + i * 16) * 80 + kk * 16], 80);
                wmma::load_matrix_sync(al[i], &u.s.Al[(wm * 32 + i * 16) * 80 + kk * 16], 80);
            }
#pragma unroll
            for (int j = 0; j < 2; j++) {
                wmma::load_matrix_sync(bh[j], &u.s.Bh[(kk * 16) * 80 + wn * 32 + j * 16], 80);
                wmma::load_matrix_sync(bl[j], &u.s.Bl[(kk * 16) * 80 + wn * 32 + j * 16], 80);
            }
#pragma unroll
            for (int i = 0; i < 2; i++)
#pragma unroll
                for (int j = 0; j < 2; j++) {
                    wmma::mma_sync(c[i][j], ah[i], bh[j], c[i][j]);
                    wmma::mma_sync(c[i][j], ah[i], bl[j], c[i][j]);
                    wmma::mma_sync(c[i][j], al[i], bh[j], c[i][j]);
                }
        }
        __syncthreads();
    }
#pragma unroll
    for (int i = 0; i < 2; i++)
#pragma unroll
        for (int j = 0; j < 2; j++)
            wmma::store_matrix_sync(&u.C[(wm * 32 + i * 16) * 64 + wn * 32 + j * 16],
                                    c[i][j], 64, wmma::mem_row_major);
    __syncthreads();
}

// GEMM unit: run core, dump 64x64 tile (scaled) to P (row stride N)
template <bool NKW>
__device__ __forceinline__ void gemm_unit(
    HU& u, const float* A, int K, const float* B, int ldB, int nk, int m0,
    float* P, int N, float scale)
{
    hmma_core<NKW>(u, A, K, B, ldB, nk, 100 - m0);
    const int t = threadIdx.x;
#pragma unroll
    for (int i = 0; i < 8; i++) {
        const int e = t + (i << 7);
        const int m = e >> 4, n4 = (e & 15) << 2;
        if (m0 + m < 100) {
            float4 v = *(float4*)&u.C[m * 64 + n4];
            v.x *= scale; v.y *= scale; v.z *= scale; v.w *= scale;
            *(float4*)&P[(size_t)m * N + n4] = v;
        }
    }
}

// combine phase: out = sum_s part[s] (+bias)(relu)(+resid)(+locemb)
__device__ __forceinline__ void combine_phase(
    const float* part, int S, int N, const float* bias,
    const float* resid, float* out, int relu, int locemb)
{
    const int total4 = 100 * N / 4;
    for (int idx = blockIdx.x * NTHR + threadIdx.x; idx < total4; idx += NCTA * NTHR) {
        const int base = idx * 4;
        const int n = base % N;
        float4 v = *(const float4*)&part[base];
        for (int s = 1; s < S; s++) {
            const float4 p = *(const float4*)&part[(size_t)s * 100 * N + base];
            v.x += p.x; v.y += p.y; v.z += p.z; v.w += p.w;
        }
        if (bias) {
            const float4 b = *(const float4*)&bias[n];
            v.x += b.x; v.y += b.y; v.z += b.z; v.w += b.w;
        }
        if (relu) {
            v.x = fmaxf(v.x, 0.f); v.y = fmaxf(v.y, 0.f);
            v.z = fmaxf(v.z, 0.f); v.w = fmaxf(v.w, 0.f);
        }
        if (resid) {
            const float4 r = *(const float4*)&resid[base];
            v.x += r.x; v.y += r.y; v.z += r.z; v.w += r.w;
        }
        if (locemb) {
            const int row = base / N;
            const float pos = 20.0f * (float)(row / 10);
            float* vp = &v.x;
#pragma unroll
            for (int j = 0; j < 4; j++) {
                const int d = n + j;
                const int k = d & 255;
                const float ang = pos * exp2f(-0.10381025296523009f * (float)k);
                vp[j] += (d < 256) ? sinf(ang) : cosf(ang);
            }
        }
        *(float4*)&out[base] = v;
    }
}

// ---------------- megakernel ----------------
__global__ __launch_bounds__(NTHR, 1) void mega_kernel(
    const float* __restrict__ cw10, const float* __restrict__ cb10,
    const float* __restrict__ Wq, const float* __restrict__ Wk,
    const float* __restrict__ Wv, const float* __restrict__ Wo,
    const float* __restrict__ W1, const float* __restrict__ b1,
    const float* __restrict__ W2, const float* __restrict__ b2,
    float* __restrict__ d_out)
{
    extern __shared__ char dsm[];
    HU& u = *(HU*)dsm;
    int lsense = 0;
    const int cta = blockIdx.x;
    const int tid = threadIdx.x;

    // ---- phase: conv10 GEMM  [100,1024] @ cw10^T  (S=8, NKW) ----
    if (cta < 128) {
        const int s = cta & 7, nt = (cta >> 3) & 7, mt = cta >> 6;
        const int m0 = mt * 64, n0 = nt * 64;
        gemm_unit<true>(u, g_bufA + (size_t)m0 * 1024 + s * 128, 1024,
                        cw10 + (size_t)n0 * 1024 + s * 128, 1024, 2, m0,
                        g_part + ((size_t)s * 100 + m0) * 512 + n0, 512, 1.0f);
    }
    gbar(&lsense);                                               // bar 1
    combine_phase(g_part, 8, 512, cb10, nullptr, g_h, 0, 1);
    gbar(&lsense);                                               // bar 2

    for (int n = 0; n < 12; n++) {
        const float* LWq = Wq + (size_t)n * 262144;
        const float* LWk = Wk + (size_t)n * 262144;
        const float* LWv = Wv + (size_t)n * 524288;
        const float* LWo = Wo + (size_t)n * 524288;
        const float* LW1 = W1 + (size_t)n * 1048576;
        const float* Lb1 = b1 + (size_t)n * 2048;
        const float* LW2 = W2 + (size_t)n * 1048576;
        const float* Lb2 = b2 + (size_t)n * 512;

        // ---- QKV: 64 units ----
        if (cta < 64) {
            const float* B;
            float* C;
            int Nc, m0, n0;
            float scale = 1.0f;
            if (cta < 16) {
                const int h4 = cta >> 2, mt = (cta >> 1) & 1, nt = cta & 1;
                Nc = 128; m0 = mt * 64; n0 = nt * 64;
                B = LWq + (size_t)h4 * 65536; C = g_q + h4 * 12800; scale = 0.1f;
            } else if (cta < 32) {
                const int v = cta - 16;
                const int h4 = v >> 2, mt = (v >> 1) & 1, nt = v & 1;
                Nc = 128; m0 = mt * 64; n0 = nt * 64;
                B = LWk + (size_t)h4 * 65536; C = g_k + h4 * 12800;
            } else {
                const int v = cta - 32;
                const int h4 = v >> 3, mt = (v >> 2) & 1, nt = v & 3;
                Nc = 256; m0 = mt * 64; n0 = nt * 64;
                B = LWv + (size_t)h4 * 131072; C = g_v + h4 * 25600;
            }
            gemm_unit<false>(u, g_h + (size_t)m0 * 512, 512, B + n0, Nc, 8, m0,
                             C + (size_t)m0 * Nc + n0, Nc, scale);
        }
        gbar(&lsense);                                           // bar 3

        // ---- attention: 40 units (head, rowgroup) ----
        if (cta < 40) {
            float* ks = (float*)dsm;              // [100][132]
            float* vs = ks + 13200;               // [100][256]
            float* qs = vs + 25600;               // [10][132]
            float* prow = qs + 1320;              // [10][104]
            const int h4 = cta / 10, rg = cta % 10;
            const int w = tid >> 5, lane = tid & 31;

            for (int idx = tid; idx < 100 * 128; idx += NTHR) {
                const int m = idx >> 7, d = idx & 127;
                ks[m * 132 + d] = g_k[h4 * 12800 + idx];
            }
            for (int idx = tid; idx < 100 * 256; idx += NTHR)
                vs[idx] = g_v[h4 * 25600 + idx];
            for (int idx = tid; idx < 10 * 128; idx += NTHR) {
                const int r = idx >> 7, d = idx & 127;
                qs[r * 132 + d] = g_q[(h4 * 100 + rg * 10 + r) * 128 + d];
            }
            __syncthreads();

            for (int r = w; r < 10; r += 4) {
                const float4* q4 = (const float4*)(qs + r * 132);
                float sc[4];
#pragma unroll
                for (int j = 0; j < 4; j++) {
                    const int m = lane + 32 * j;
                    if (m < 100) {
                        const float4* k4 = (const float4*)(ks + m * 132);
                        float acc = 0.0f;
#pragma unroll
                        for (int dd = 0; dd < 32; dd++) {
                            const float4 kv = k4[dd];
                            const float4 qv = q4[dd];
                            acc += qv.x * kv.x + qv.y * kv.y + qv.z * kv.z + qv.w * kv.w;
                        }
                        sc[j] = acc;
                    } else sc[j] = -1e30f;
                }
                float mx = fmaxf(fmaxf(sc[0], sc[1]), fmaxf(sc[2], sc[3]));
#pragma unroll
                for (int o = 16; o; o >>= 1) mx = fmaxf(mx, __shfl_xor_sync(0xffffffffu, mx, o));
                float e[4], sum = 0.0f;
#pragma unroll
                for (int j = 0; j < 4; j++) { e[j] = __expf(sc[j] - mx); sum += e[j]; }
#pragma unroll
                for (int o = 16; o; o >>= 1) sum += __shfl_xor_sync(0xffffffffu, sum, o);
                const float inv = 1.0f / sum;
#pragma unroll
                for (int j = 0; j < 4; j++) {
                    const int m = lane + 32 * j;
                    if (m < 100) prow[r * 104 + m] = e[j] * inv;
                }
                __syncwarp();

                float acc[8] = {};
                const float* pr = prow + r * 104;
#pragma unroll 4
                for (int m = 0; m < 100; m++) {
                    const float p = pr[m];
                    const float* vr = vs + m * 256 + lane;
#pragma unroll
                    for (int j = 0; j < 8; j++) acc[j] += p * vr[32 * j];
                }
                const int row = rg * 10 + r;
                float* orow = g_ocat + row * 1024 + h4 * 256 + lane;
#pragma unroll
                for (int j = 0; j < 8; j++) orow[32 * j] = acc[j];
            }
        }
        gbar(&lsense);                                           // bar 4

        // ---- Wo GEMM: S=8, 128 units ----
        {
            const int s = cta & 7, nt = (cta >> 3) & 7, mt = cta >> 6;
            const int m0 = mt * 64, n0 = nt * 64;
            gemm_unit<false>(u, g_ocat + (size_t)m0 * 1024 + s * 128, 1024,
                             LWo + (size_t)(s * 128) * 512 + n0, 512, 2, m0,
                             g_part + ((size_t)s * 100 + m0) * 512 + n0, 512, 1.0f);
        }
        gbar(&lsense);                                           // bar 5
        combine_phase(g_part, 8, 512, nullptr, g_h, g_h, 0, 0);
        gbar(&lsense);                                           // bar 6

        // ---- FFN1 GEMM: S=2, 128 units ----
        {
            const int s = cta & 1, nt = (cta >> 1) & 31, mt = cta >> 6;
            const int m0 = mt * 64, n0 = nt * 64;
            gemm_unit<false>(u, g_h + (size_t)m0 * 512 + s * 256, 512,
                             LW1 + (size_t)(s * 256) * 2048 + n0, 2048, 4, m0,
                             g_part + ((size_t)s * 100 + m0) * 2048 + n0, 2048, 1.0f);
        }
        gbar(&lsense);                                           // bar 7
        combine_phase(g_part, 2, 2048, Lb1, nullptr, g_ffn, 1, 0);
        gbar(&lsense);                                           // bar 8

        // ---- FFN2 GEMM: S=8, 128 units ----
        {
            const int s = cta & 7, nt = (cta >> 3) & 7, mt = cta >> 6;
            const int m0 = mt * 64, n0 = nt * 64;
            gemm_unit<false>(u, g_ffn + (size_t)m0 * 2048 + s * 256, 2048,
                             LW2 + (size_t)(s * 256) * 512 + n0, 512, 4, m0,
                             g_part + ((size_t)s * 100 + m0) * 512 + n0, 512, 1.0f);
        }
        gbar(&lsense);                                           // bar 9
        combine_phase(g_part, 8, 512, Lb2, g_h, (n == 11) ? d_out : g_h, 0, 0);
        gbar(&lsense);                                           // bar 10
    }
}

// ---------------- conv layers 1-9 (row-strip kernel) ----------------
template <int CIN, int HIN, int COUT, int KS, int COG, bool RELU, bool FIRST>
__global__ __launch_bounds__(128) void conv_kernel(
    const float* __restrict__ in, const float* __restrict__ W,
    const float* __restrict__ bias, float* __restrict__ out)
{
    constexpr int HOUT = HIN - KS + 1;
    constexpr int WOUT = HOUT;
    constexpr int INSZ = CIN * HIN * HIN;
    constexpr int HW = HOUT * WOUT;
    __shared__ float sin_[INSZ];

    const int p = blockIdx.x;
    const int co0 = blockIdx.y * COG;

    if (FIRST) {
        const int ib = p / 10, jb = p % 10;
        for (int idx = threadIdx.x; idx < INSZ; idx += blockDim.x) {
            const int c = idx / (HIN * HIN);
            const int rem = idx % (HIN * HIN);
            const int r = rem / HIN, cc = rem % HIN;
            sin_[idx] = in[c * 40000 + (20 * jb + r) * 200 + (20 * ib + cc)];
        }
    } else {
        const float* src = in + p * INSZ;
        for (int idx = threadIdx.x; idx < INSZ; idx += blockDim.x)
            sin_[idx] = src[idx];
    }
    __syncthreads();

    for (int pair = threadIdx.x; pair < COG * HOUT; pair += blockDim.x) {
        const int co = co0 + pair / HOUT;
        const int py = pair % HOUT;
        float acc[WOUT];
        const float bv = bias[co];
#pragma unroll
        for (int px = 0; px < WOUT; px++) acc[px] = bv;
        const float* wbase = W + co * CIN * KS * KS;
        for (int ci = 0; ci < CIN; ci++) {
#pragma unroll
            for (int ky = 0; ky < KS; ky++) {
                const float* irow = sin_ + ci * HIN * HIN + (py + ky) * HIN;
                float w[KS];
#pragma unroll
                for (int kx = 0; kx < KS; kx++)
                    w[kx] = wbase[ci * KS * KS + ky * KS + kx];
#pragma unroll
                for (int px = 0; px < WOUT; px++) {
#pragma unroll
                    for (int kx = 0; kx < KS; kx++)
                        acc[px] += w[kx] * irow[px + kx];
                }
            }
        }
        float* orow = out + p * COUT * HW + co * HW + py * WOUT;
#pragma unroll
        for (int px = 0; px < WOUT; px++) {
            float v = acc[px];
            if (RELU) v = fmaxf(v, 0.0f);
            orow[px] = v;
        }
    }
}

// ---------------- launch ----------------
extern "C" void kernel_launch(void* const* d_in, const int* in_sizes, int n_in,
                              void* d_out, int out_size)
{
    (void)in_sizes; (void)n_in; (void)out_size;
    const float* x = (const float*)d_in[0];
    const float* cw[10];
    const float* cb[10];
    for (int i = 0; i < 10; i++) {
        cw[i] = (const float*)d_in[1 + 2 * i];
        cb[i] = (const float*)d_in[2 + 2 * i];
    }
    const float* Wq = (const float*)d_in[21];
    const float* Wk = (const float*)d_in[22];
    const float* Wv = (const float*)d_in[23];
    const float* Wo = (const float*)d_in[24];
    const float* W1 = (const float*)d_in[25];
    const float* b1 = (const float*)d_in[26];
    const float* W2 = (const float*)d_in[27];
    const float* b2 = (const float*)d_in[28];

    float *bufA, *bufB;
    cudaGetSymbolAddress((void**)&bufA, g_bufA);
    cudaGetSymbolAddress((void**)&bufB, g_bufB);

    cudaFuncSetAttribute(mega_kernel, cudaFuncAttributeMaxDynamicSharedMemorySize, DSM_BYTES);

    // Conv stack (RELU_AFTER = F T F T T T T T T F); conv9 output -> bufA
    conv_kernel<3, 20, 8, 3, 8, false, true><<<dim3(100, 1), 128>>>(x, cw[0], cb[0], bufA);
    conv_kernel<8, 18, 16, 3, 8, true, false><<<dim3(100, 2), 128>>>(bufA, cw[1], cb[1], bufB);
    conv_kernel<16, 16, 32, 3, 8, false, false><<<dim3(100, 4), 128>>>(bufB, cw[2], cb[2], bufA);
    conv_kernel<32, 14, 32, 3, 8, true, false><<<dim3(100, 4), 128>>>(bufA, cw[3], cb[3], bufB);
    conv_kernel<32, 12, 64, 3, 16, true, false><<<dim3(100, 4), 128>>>(bufB, cw[4], cb[4], bufA);
    conv_kernel<64, 10, 64, 3, 16, true, false><<<dim3(100, 4), 128>>>(bufA, cw[5], cb[5], bufB);
    conv_kernel<64, 8, 128, 3, 32, true, false><<<dim3(100, 4), 128>>>(bufB, cw[6], cb[6], bufA);
    conv_kernel<128, 6, 128, 3, 32, true, false><<<dim3(100, 4), 128>>>(bufA, cw[7], cb[7], bufB);
    conv_kernel<128, 4, 256, 3, 64, true, false><<<dim3(100, 4), 128>>>(bufB, cw[8], cb[8], bufA);

    // conv10 + locadd + 12 encoder layers in one persistent kernel
    mega_kernel<<<NCTA, NTHR, DSM_BYTES>>>(cw[9], cb[9], Wq, Wk, Wv, Wo,
                                           W1, b1, W2, b2, (float*)d_out);
}

// round 10
// speedup vs baseline: 1.4181x; 1.2007x over previous
#include <cuda_runtime.h>
#include <cuda_bf16.h>
#include <mma.h>
#include <math.h>
#include <stdint.h>

using namespace nvcuda;

// ---------------- scratch (allocation-free: __device__ globals) ----------------
__device__ float g_bufA[660000];
__device__ float g_bufB[660000];
__device__ float g_h[100 * 512];
__device__ float g_q[100 * 512];    // [100][h*128+d]
__device__ float g_k[100 * 512];
__device__ float g_v[100 * 1024];   // [100][h*256+dv]
__device__ float g_ocat[100 * 1024];
__device__ float g_ffn[100 * 2048];
__device__ float g_part[819200];
__device__ int g_count = 0;
__device__ volatile int g_sense = 0;

#define NCTA 128
#define NTHR 256
#define DSM_BYTES 168960
#define HU_BYTES 40960

// ---------------- global barrier (sense-reversing; even count per launch) ----
__device__ __forceinline__ void gbar(int* lsense) {
    __syncthreads();
    if (threadIdx.x == 0) {
        __threadfence();
        *lsense ^= 1;
        if (atomicAdd(&g_count, 1) == NCTA - 1) {
            g_count = 0;
            __threadfence();
            g_sense = *lsense;
        } else {
            while (g_sense != *lsense) __nanosleep(32);
        }
        __threadfence();
    }
    __syncthreads();
}

// ================= HMMA core (per-half: 128 threads, 64x64 tile) =============
struct __align__(32) HSM {
    __nv_bfloat16 Ah[64 * 80];
    __nv_bfloat16 Al[64 * 80];
    __nv_bfloat16 Bh[64 * 80];
    __nv_bfloat16 Bl[64 * 80];
};
union __align__(32) HU {
    HSM s;
    float C[64 * 64];
};

__device__ __forceinline__ uint32_t bf2pack(__nv_bfloat16 a, __nv_bfloat16 b) {
    __nv_bfloat162 t(a, b);
    return *reinterpret_cast<uint32_t*>(&t);
}

template <bool NKW>
__device__ __forceinline__ void hmma_core(
    HU& u, int t, const float* __restrict__ A, int K,
    const float* __restrict__ B, int ldB, int nk, int mvalid)
{
    const int wid = t >> 5;
    const int wm = wid >> 1, wn = wid & 1;

    wmma::fragment<wmma::accumulator, 16, 16, 16, float> c[2][2];
#pragma unroll
    for (int i = 0; i < 2; i++)
#pragma unroll
        for (int j = 0; j < 2; j++) wmma::fill_fragment(c[i][j], 0.0f);

    for (int kt = 0; kt < nk; kt++) {
        const int k0 = kt << 6;
#pragma unroll
        for (int i = 0; i < 8; i++) {
            const int e = t + (i << 7);
            const int m = e >> 4, k4 = (e & 15) << 2;
            float4 v = make_float4(0.f, 0.f, 0.f, 0.f);
            if (m < mvalid) v = *(const float4*)(A + (size_t)m * K + k0 + k4);
            const __nv_bfloat16 h0 = __float2bfloat16_rn(v.x), h1 = __float2bfloat16_rn(v.y),
                                h2 = __float2bfloat16_rn(v.z), h3 = __float2bfloat16_rn(v.w);
            uint2 uh, ul;
            uh.x = bf2pack(h0, h1); uh.y = bf2pack(h2, h3);
            ul.x = bf2pack(__float2bfloat16_rn(v.x - __bfloat162float(h0)),
                           __float2bfloat16_rn(v.y - __bfloat162float(h1)));
            ul.y = bf2pack(__float2bfloat16_rn(v.z - __bfloat162float(h2)),
                           __float2bfloat16_rn(v.w - __bfloat162float(h3)));
            *(uint2*)&u.s.Ah[m * 80 + k4] = uh;
            *(uint2*)&u.s.Al[m * 80 + k4] = ul;
        }
#pragma unroll
        for (int i = 0; i < 8; i++) {
            const int e = t + (i << 7);
            if (!NKW) {
                const int k = e >> 4, n4 = (e & 15) << 2;
                const float4 v = *(const float4*)(B + (size_t)(k0 + k) * ldB + n4);
                const __nv_bfloat16 h0 = __float2bfloat16_rn(v.x), h1 = __float2bfloat16_rn(v.y),
                                    h2 = __float2bfloat16_rn(v.z), h3 = __float2bfloat16_rn(v.w);
                uint2 uh, ul;
                uh.x = bf2pack(h0, h1); uh.y = bf2pack(h2, h3);
                ul.x = bf2pack(__float2bfloat16_rn(v.x - __bfloat162float(h0)),
                               __float2bfloat16_rn(v.y - __bfloat162float(h1)));
                ul.y = bf2pack(__float2bfloat16_rn(v.z - __bfloat162float(h2)),
                               __float2bfloat16_rn(v.w - __bfloat162float(h3)));
                *(uint2*)&u.s.Bh[k * 80 + n4] = uh;
                *(uint2*)&u.s.Bl[k * 80 + n4] = ul;
            } else {
                const int n = e >> 4, k4 = (e & 15) << 2;
                const float4 v = *(const float4*)(B + (size_t)n * ldB + k0 + k4);
                const float vv[4] = {v.x, v.y, v.z, v.w};
#pragma unroll
                for (int j = 0; j < 4; j++) {
                    const __nv_bfloat16 hb = __float2bfloat16_rn(vv[j]);
                    u.s.Bh[(k4 + j) * 80 + n] = hb;
                    u.s.Bl[(k4 + j) * 80 + n] =
                        __float2bfloat16_rn(vv[j] - __bfloat162float(hb));
                }
            }
        }
        __syncthreads();
#pragma unroll
        for (int kk = 0; kk < 4; kk++) {
            wmma::fragment<wmma::matrix_a, 16, 16, 16, __nv_bfloat16, wmma::row_major> ah[2], al[2];
            wmma::fragment<wmma::matrix_b, 16, 16, 16, __nv_bfloat16, wmma::row_major> bh[2], bl[2];
#pragma unroll
            for (int i = 0; i < 2; i++) {
                wmma::load_matrix_sync(ah[i], &u.s.Ah[(wm * 32 + i * 16) * 80 + kk * 16], 80);
                wmma::load_matrix_sync(al[i], &u.s.Al[(wm * 32 + i * 16) * 80 + kk * 16], 80);
            }
#pragma unroll
            for (int j = 0; j < 2; j++) {
                wmma::load_matrix_sync(bh[j], &u.s.Bh[(kk * 16) * 80 + wn * 32 + j * 16], 80);
                wmma::load_matrix_sync(bl[j], &u.s.Bl[(kk * 16) * 80 + wn * 32 + j * 16], 80);
            }
#pragma unroll
            for (int i = 0; i < 2; i++)
#pragma unroll
                for (int j = 0; j < 2; j++) {
                    wmma::mma_sync(c[i][j], ah[i], bh[j], c[i][j]);
                    wmma::mma_sync(c[i][j], ah[i], bl[j], c[i][j]);
                    wmma::mma_sync(c[i][j], al[i], bh[j], c[i][j]);
                }
        }
        __syncthreads();
    }
#pragma unroll
    for (int i = 0; i < 2; i++)
#pragma unroll
        for (int j = 0; j < 2; j++)
            wmma::store_matrix_sync(&u.C[(wm * 32 + i * 16) * 64 + wn * 32 + j * 16],
                                    c[i][j], 64, wmma::mem_row_major);
    __syncthreads();
}

template <bool NKW>
__device__ __forceinline__ void gemm_unit(
    HU& u, int t, const float* A, int K, const float* B, int ldB, int nk, int m0,
    float* P, int N)
{
    hmma_core<NKW>(u, t, A, K, B, ldB, nk, 100 - m0);
#pragma unroll
    for (int i = 0; i < 8; i++) {
        const int e = t + (i << 7);
        const int m = e >> 4, n4 = (e & 15) << 2;
        if (m0 + m < 100)
            *(float4*)&P[(size_t)m * N + n4] = *(float4*)&u.C[m * 64 + n4];
    }
}

// combine: out = sum_s part[s]; mode 0 plain, 1 +locemb, 2 qkv-dispatch
__device__ __forceinline__ void combine_phase(
    const float* part, int S, int N, const float* bias,
    const float* resid, float* out, int relu, int mode)
{
    const int total4 = 100 * N / 4;
    for (int idx = blockIdx.x * NTHR + threadIdx.x; idx < total4; idx += NCTA * NTHR) {
        const int base = idx * 4;
        const int n = base % N;
        const int row = base / N;
        float4 v = *(const float4*)&part[base];
        for (int s = 1; s < S; s++) {
            const float4 p = *(const float4*)&part[(size_t)s * 100 * N + base];
            v.x += p.x; v.y += p.y; v.z += p.z; v.w += p.w;
        }
        if (mode == 2) {
            if (n < 512) {
                v.x *= 0.1f; v.y *= 0.1f; v.z *= 0.1f; v.w *= 0.1f;
                *(float4*)&g_q[row * 512 + n] = v;
            } else if (n < 1024) {
                *(float4*)&g_k[row * 512 + n - 512] = v;
            } else {
                *(float4*)&g_v[row * 1024 + n - 1024] = v;
            }
            continue;
        }
        if (bias) {
            const float4 b = *(const float4*)&bias[n];
            v.x += b.x; v.y += b.y; v.z += b.z; v.w += b.w;
        }
        if (relu) {
            v.x = fmaxf(v.x, 0.f); v.y = fmaxf(v.y, 0.f);
            v.z = fmaxf(v.z, 0.f); v.w = fmaxf(v.w, 0.f);
        }
        if (resid) {
            const float4 r = *(const float4*)&resid[base];
            v.x += r.x; v.y += r.y; v.z += r.z; v.w += r.w;
        }
        if (mode == 1) {
            const float pos = 20.0f * (float)(row / 10);
            float* vp = &v.x;
#pragma unroll
            for (int j = 0; j < 4; j++) {
                const int d = n + j;
                const int k = d & 255;
                const float ang = pos * exp2f(-0.10381025296523009f * (float)k);
                vp[j] += (d < 256) ? sinf(ang) : cosf(ang);
            }
        }
        *(float4*)&out[base] = v;
    }
}

// ---------------- megakernel ----------------
__global__ __launch_bounds__(NTHR, 1) void mega_kernel(
    const float* __restrict__ cw10, const float* __restrict__ cb10,
    const float* __restrict__ Wq, const float* __restrict__ Wk,
    const float* __restrict__ Wv, const float* __restrict__ Wo,
    const float* __restrict__ W1, const float* __restrict__ b1,
    const float* __restrict__ W2, const float* __restrict__ b2,
    float* __restrict__ d_out)
{
    extern __shared__ char dsm[];
    int lsense = 0;
    const int cta = blockIdx.x;
    const int tid = threadIdx.x;
    const int half = tid >> 7;
    const int lt = tid & 127;
    HU& u = *(HU*)(dsm + half * HU_BYTES);
    const int unit = cta * 2 + half;

    // ---- conv10: [100,1024] @ cw10^T, S=16, nk=1 (256 units) ----
    {
        const int s = unit & 15, nt = (unit >> 4) & 7, mt = unit >> 7;
        const int m0 = mt * 64, n0 = nt * 64;
        gemm_unit<true>(u, lt, g_bufA + (size_t)m0 * 1024 + s * 64, 1024,
                        cw10 + (size_t)n0 * 1024 + s * 64, 1024, 1, m0,
                        g_part + ((size_t)s * 100 + m0) * 512 + n0, 512);
    }
    gbar(&lsense);                                               // bar 1
    combine_phase(g_part, 16, 512, cb10, nullptr, g_h, 0, 1);
    gbar(&lsense);                                               // bar 2

    for (int n = 0; n < 12; n++) {
        const float* LWq = Wq + (size_t)n * 262144;
        const float* LWk = Wk + (size_t)n * 262144;
        const float* LWv = Wv + (size_t)n * 524288;
        const float* LWo = Wo + (size_t)n * 524288;
        const float* LW1 = W1 + (size_t)n * 1048576;
        const float* Lb1 = b1 + (size_t)n * 2048;
        const float* LW2 = W2 + (size_t)n * 1048576;
        const float* Lb2 = b2 + (size_t)n * 512;

        // ---- QKV: concat out [100,2048], S=4, nk=2 (256 units) ----
        {
            const int s = unit & 3, nt = (unit >> 2) & 31, mt = unit >> 7;
            const int m0 = mt * 64;
            const int col0 = nt * 64;
            const float* Bp;
            int ldB2;
            if (col0 < 512) {
                const int hh = col0 >> 7, nin = col0 & 127;
                Bp = LWq + (size_t)hh * 65536 + s * 16384 + nin; ldB2 = 128;
            } else if (col0 < 1024) {
                const int c = col0 - 512, hh = c >> 7, nin = c & 127;
                Bp = LWk + (size_t)hh * 65536 + s * 16384 + nin; ldB2 = 128;
            } else {
                const int c = col0 - 1024, hh = c >> 8, nin = c & 255;
                Bp = LWv + (size_t)hh * 131072 + s * 32768 + nin; ldB2 = 256;
            }
            gemm_unit<false>(u, lt, g_h + (size_t)m0 * 512 + s * 128, 512,
                             Bp, ldB2, 2, m0,
                             g_part + ((size_t)s * 100 + m0) * 2048 + col0, 2048);
        }
        gbar(&lsense);                                           // bar 3
        combine_phase(g_part, 4, 2048, nullptr, nullptr, nullptr, 0, 2);
        gbar(&lsense);                                           // bar 4

        // ---- attention: 40 whole-CTA units ----
        if (cta < 40) {
            float* ks = (float*)dsm;               // [100][132]
            float* vs = ks + 13200;                // [100][256]
            float* qs = vs + 25600;                // [10][132]
            float* prow = qs + 1320;               // [10][104]
            const int h4 = cta / 10, rg = cta % 10;
            const int w = tid >> 5, lane = tid & 31;

            for (int idx = tid; idx < 100 * 128; idx += NTHR) {
                const int m = idx >> 7, d = idx & 127;
                ks[m * 132 + d] = g_k[m * 512 + h4 * 128 + d];
            }
            for (int idx = tid; idx < 100 * 256; idx += NTHR) {
                const int m = idx >> 8, dv = idx & 255;
                vs[idx] = g_v[m * 1024 + h4 * 256 + dv];
            }
            for (int idx = tid; idx < 10 * 128; idx += NTHR) {
                const int r = idx >> 7, d = idx & 127;
                qs[r * 132 + d] = g_q[(rg * 10 + r) * 512 + h4 * 128 + d];
            }
            __syncthreads();

#pragma unroll
            for (int rr = 0; rr < 2; rr++) {
                const int r = w + rr * 8;
                if (r >= 10) break;
                const float4* q4 = (const float4*)(qs + r * 132);
                float sc[4];
#pragma unroll
                for (int j = 0; j < 4; j++) {
                    const int m = lane + 32 * j;
                    if (m < 100) {
                        const float4* k4 = (const float4*)(ks + m * 132);
                        float acc = 0.0f;
#pragma unroll
                        for (int dd = 0; dd < 32; dd++) {
                            const float4 kv = k4[dd];
                            const float4 qv = q4[dd];
                            acc += qv.x * kv.x + qv.y * kv.y + qv.z * kv.z + qv.w * kv.w;
                        }
                        sc[j] = acc;
                    } else sc[j] = -1e30f;
                }
                float mx = fmaxf(fmaxf(sc[0], sc[1]), fmaxf(sc[2], sc[3]));
#pragma unroll
                for (int o = 16; o; o >>= 1) mx = fmaxf(mx, __shfl_xor_sync(0xffffffffu, mx, o));
                float e[4], sum = 0.0f;
#pragma unroll
                for (int j = 0; j < 4; j++) { e[j] = __expf(sc[j] - mx); sum += e[j]; }
#pragma unroll
                for (int o = 16; o; o >>= 1) sum += __shfl_xor_sync(0xffffffffu, sum, o);
                const float inv = 1.0f / sum;
#pragma unroll
                for (int j = 0; j < 4; j++) {
                    const int m = lane + 32 * j;
                    if (m < 100) prow[r * 104 + m] = e[j] * inv;
                }
                __syncwarp();

                float acc[8] = {};
                const float* pr = prow + r * 104;
#pragma unroll 4
                for (int m = 0; m < 100; m++) {
                    const float p = pr[m];
                    const float* vr = vs + m * 256 + lane;
#pragma unroll
                    for (int j = 0; j < 8; j++) acc[j] += p * vr[32 * j];
                }
                const int row = rg * 10 + r;
                float* orow = g_ocat + row * 1024 + h4 * 256 + lane;
#pragma unroll
                for (int j = 0; j < 8; j++) orow[32 * j] = acc[j];
            }
        }
        gbar(&lsense);                                           // bar 5

        // ---- Wo: [100,1024]x[1024,512], S=16, nk=1 ----
        {
            const int s = unit & 15, nt = (unit >> 4) & 7, mt = unit >> 7;
            const int m0 = mt * 64, n0 = nt * 64;
            gemm_unit<false>(u, lt, g_ocat + (size_t)m0 * 1024 + s * 64, 1024,
                             LWo + (size_t)(s * 64) * 512 + n0, 512, 1, m0,
                             g_part + ((size_t)s * 100 + m0) * 512 + n0, 512);
        }
        gbar(&lsense);                                           // bar 6
        combine_phase(g_part, 16, 512, nullptr, g_h, g_h, 0, 0);
        gbar(&lsense);                                           // bar 7

        // ---- FFN1: [100,512]x[512,2048], S=4, nk=2 ----
        {
            const int s = unit & 3, nt = (unit >> 2) & 31, mt = unit >> 7;
            const int m0 = mt * 64, n0 = nt * 64;
            gemm_unit<false>(u, lt, g_h + (size_t)m0 * 512 + s * 128, 512,
                             LW1 + (size_t)(s * 128) * 2048 + n0, 2048, 2, m0,
                             g_part + ((size_t)s * 100 + m0) * 2048 + n0, 2048);
        }
        gbar(&lsense);                                           // bar 8
        combine_phase(g_part, 4, 2048, Lb1, nullptr, g_ffn, 1, 0);
        gbar(&lsense);                                           // bar 9

        // ---- FFN2: [100,2048]x[2048,512], S=16, nk=2 ----
        {
            const int s = unit & 15, nt = (unit >> 4) & 7, mt = unit >> 7;
            const int m0 = mt * 64, n0 = nt * 64;
            gemm_unit<false>(u, lt, g_ffn + (size_t)m0 * 2048 + s * 128, 2048,
                             LW2 + (size_t)(s * 128) * 512 + n0, 512, 2, m0,
                             g_part + ((size_t)s * 100 + m0) * 512 + n0, 512);
        }
        gbar(&lsense);                                           // bar 10
        combine_phase(g_part, 16, 512, Lb2, g_h, (n == 11) ? d_out : g_h, 0, 0);
        gbar(&lsense);                                           // bar 11
    }
}

// ---------------- conv layers 1-9 (row-strip kernel) ----------------
template <int CIN, int HIN, int COUT, int KS, int COG, bool RELU, bool FIRST>
__global__ __launch_bounds__(128) void conv_kernel(
    const float* __restrict__ in, const float* __restrict__ W,
    const float* __restrict__ bias, float* __restrict__ out)
{
    constexpr int HOUT = HIN - KS + 1;
    constexpr int WOUT = HOUT;
    constexpr int INSZ = CIN * HIN * HIN;
    constexpr int HW = HOUT * WOUT;
    __shared__ float sin_[INSZ];

    const int p = blockIdx.x;
    const int co0 = blockIdx.y * COG;

    if (FIRST) {
        const int ib = p / 10, jb = p % 10;
        for (int idx = threadIdx.x; idx < INSZ; idx += blockDim.x) {
            const int c = idx / (HIN * HIN);
            const int rem = idx % (HIN * HIN);
            const int r = rem / HIN, cc = rem % HIN;
            sin_[idx] = in[c * 40000 + (20 * jb + r) * 200 + (20 * ib + cc)];
        }
    } else {
        const float* src = in + p * INSZ;
        for (int idx = threadIdx.x; idx < INSZ; idx += blockDim.x)
            sin_[idx] = src[idx];
    }
    __syncthreads();

    for (int pair = threadIdx.x; pair < COG * HOUT; pair += blockDim.x) {
        const int co = co0 + pair / HOUT;
        const int py = pair % HOUT;
        float acc[WOUT];
        const float bv = bias[co];
#pragma unroll
        for (int px = 0; px < WOUT; px++) acc[px] = bv;
        const float* wbase = W + co * CIN * KS * KS;
        for (int ci = 0; ci < CIN; ci++) {
#pragma unroll
            for (int ky = 0; ky < KS; ky++) {
                const float* irow = sin_ + ci * HIN * HIN + (py + ky) * HIN;
                float w[KS];
#pragma unroll
                for (int kx = 0; kx < KS; kx++)
                    w[kx] = wbase[ci * KS * KS + ky * KS + kx];
#pragma unroll
                for (int px = 0; px < WOUT; px++) {
#pragma unroll
                    for (int kx = 0; kx < KS; kx++)
                        acc[px] += w[kx] * irow[px + kx];
                }
            }
        }
        float* orow = out + p * COUT * HW + co * HW + py * WOUT;
#pragma unroll
        for (int px = 0; px < WOUT; px++) {
            float v = acc[px];
            if (RELU) v = fmaxf(v, 0.0f);
            orow[px] = v;
        }
    }
}

// ---------------- launch ----------------
extern "C" void kernel_launch(void* const* d_in, const int* in_sizes, int n_in,
                              void* d_out, int out_size)
{
    (void)in_sizes; (void)n_in; (void)out_size;
    const float* x = (const float*)d_in[0];
    const float* cw[10];
    const float* cb[10];
    for (int i = 0; i < 10; i++) {
        cw[i] = (const float*)d_in[1 + 2 * i];
        cb[i] = (const float*)d_in[2 + 2 * i];
    }
    const float* Wq = (const float*)d_in[21];
    const float* Wk = (const float*)d_in[22];
    const float* Wv = (const float*)d_in[23];
    const float* Wo = (const float*)d_in[24];
    const float* W1 = (const float*)d_in[25];
    const float* b1 = (const float*)d_in[26];
    const float* W2 = (const float*)d_in[27];
    const float* b2 = (const float*)d_in[28];

    float *bufA, *bufB;
    cudaGetSymbolAddress((void**)&bufA, g_bufA);
    cudaGetSymbolAddress((void**)&bufB, g_bufB);

    cudaFuncSetAttribute(mega_kernel, cudaFuncAttributeMaxDynamicSharedMemorySize, DSM_BYTES);

    // Conv stack (RELU_AFTER = F T F T T T T T T F); conv9 output -> bufA
    conv_kernel<3, 20, 8, 3, 8, false, true><<<dim3(100, 1), 128>>>(x, cw[0], cb[0], bufA);
    conv_kernel<8, 18, 16, 3, 8, true, false><<<dim3(100, 2), 128>>>(bufA, cw[1], cb[1], bufB);
    conv_kernel<16, 16, 32, 3, 8, false, false><<<dim3(100, 4), 128>>>(bufB, cw[2], cb[2], bufA);
    conv_kernel<32, 14, 32, 3, 8, true, false><<<dim3(100, 4), 128>>>(bufA, cw[3], cb[3], bufB);
    conv_kernel<32, 12, 64, 3, 16, true, false><<<dim3(100, 4), 128>>>(bufB, cw[4], cb[4], bufA);
    conv_kernel<64, 10, 64, 3, 16, true, false><<<dim3(100, 4), 128>>>(bufA, cw[5], cb[5], bufB);
    conv_kernel<64, 8, 128, 3, 32, true, false><<<dim3(100, 4), 128>>>(bufB, cw[6], cb[6], bufA);
    conv_kernel<128, 6, 128, 3, 32, true, false><<<dim3(100, 4), 128>>>(bufA, cw[7], cb[7], bufB);
    conv_kernel<128, 4, 256, 3, 64, true, false><<<dim3(100, 4), 128>>>(bufB, cw[8], cb[8], bufA);

    // conv10 + locadd + 12 encoder layers in one persistent kernel
    mega_kernel<<<NCTA, NTHR, DSM_BYTES>>>(cw[9], cb[9], Wq, Wk, Wv, Wo,
                                           W1, b1, W2, b2, (float*)d_out);
}